// round 16
// baseline (speedup 1.0000x reference)
#include <cuda_runtime.h>

// Unpool_LS: 2x2 block learned-sparsity unpool.
// x0: [8,256,256,64] f32, x1: [8,128,128,64] f32
// outputs concatenated into d_out:
//   out0 [8,256,256,64], repl [8,128,128,64], out3 [8,256,256,64]
//
// R16: R15 (streaming hints, clean codegen) + ILP=2. Each thread handles TWO
// channel-quads (cq, cq+8) of one 2x2 block; all 10 loads front-batched ->
// MLP_p1=10 (2x outstanding reads per warp), grid halves to 4096. Two SOLVE
// instances on distinct named variables -- nothing address-taken, no local mem.

#define BB   8
#define HH   256
#define WW   256
#define CC   64
#define hh2  128
#define ww2  128
#define C4   (CC / 4)   // 16 float4 per position

// Solve one scalar channel (member MEM of five float4 vars), in place.
#define SOLVE(A0, A1, A2, A3, PV, FR, MASK, MEM, SH) do {                     \
    float v0 = A0.MEM, v1 = A1.MEM, v2 = A2.MEM, v3 = A3.MEM;                 \
    /* stable descending rank (mask only) */                                  \
    int r0 = (int)(v1 >  v0) + (int)(v2 >  v0) + (int)(v3 >  v0);             \
    int r1 = (int)(v0 >= v1) + (int)(v2 >  v1) + (int)(v3 >  v1);             \
    int r2 = (int)(v0 >= v2) + (int)(v1 >= v2) + (int)(v3 >  v2);             \
    int r3 = (int)(v0 >= v3) + (int)(v1 >= v3) + (int)(v2 >= v3);             \
    /* sorted descending via branchless network (FMNMX only) */               \
    float hi01 = fmaxf(v0, v1), lo01 = fminf(v0, v1);                         \
    float hi23 = fmaxf(v2, v3), lo23 = fminf(v2, v3);                         \
    float sv0  = fmaxf(hi01, hi23), mhi = fminf(hi01, hi23);                  \
    float sv3  = fminf(lo01, lo23), mlo = fmaxf(lo01, lo23);                  \
    float sv1  = fmaxf(mhi, mlo),   sv2 = fminf(mhi, mlo);                    \
    /* avg[k] = (prefix+x1)/(k+2); first-max argmax (strict >) */             \
    float x1v  = PV.MEM;                                                      \
    float s    = sv0;                                                         \
    float best = (s + x1v) * 0.5f;  /* /2 == *0.5f, IEEE-identical */         \
    int   kb   = 0;                                                           \
    float avg;                                                                \
    s += sv1; avg = (s + x1v) / 3.0f;  if (avg > best) { best = avg; kb = 1; }\
    s += sv2; avg = (s + x1v) * 0.25f; if (avg > best) { best = avg; kb = 2; }\
    s += sv3; avg = (s + x1v) / 5.0f;  if (avg > best) { best = avg; kb = 3; }\
    PV.MEM = best;                                                            \
    FR.MEM = (float)(kb + 1) / (float)(kb + 2);                               \
    bool m0 = r0 <= kb, m1 = r1 <= kb, m2 = r2 <= kb, m3 = r3 <= kb;          \
    A0.MEM = m0 ? best : v0;                                                  \
    A1.MEM = m1 ? best : v1;                                                  \
    A2.MEM = m2 ? best : v2;                                                  \
    A3.MEM = m3 ? best : v3;                                                  \
    MASK |= ((unsigned)m0 | ((unsigned)m1 << 1) |                             \
             ((unsigned)m2 << 2) | ((unsigned)m3 << 3)) << (SH);              \
} while (0)

// Build the out3 float4 for block-position p (0..3) from MASK + FR.
#define OUT3_VEC(F, MASK, FR, P) do {                                         \
    F.x = (MASK & (1u << (0 + (P)))) ? FR.x : 1.0f;                           \
    F.y = (MASK & (1u << (4 + (P)))) ? FR.y : 1.0f;                           \
    F.z = (MASK & (1u << (8 + (P)))) ? FR.z : 1.0f;                           \
    F.w = (MASK & (1u << (12 + (P)))) ? FR.w : 1.0f;                          \
} while (0)

__global__ void __launch_bounds__(256)
unpool_ls_kernel(const float4 *__restrict__ x0,
                 const float4 *__restrict__ x1,
                 float4 *__restrict__ out0,
                 float4 *__restrict__ out1,
                 float4 *__restrict__ out2) {
    int t = blockIdx.x * blockDim.x + threadIdx.x;   // [0, 131072*8)
    int cq  = t & 7;             // channel quad 0..7 (second half: +8)
    int blk = t >> 3;            // linear (b,h,w) block index, 0..131071

    int w = blk & (ww2 - 1);
    int h = (blk >> 7) & (hh2 - 1);
    int b = blk >> 14;

    int pos = ((b * HH + 2 * h) * WW + 2 * w);       // position index in x0
    int i00 = pos * C4 + cq;
    int i01 = i00 + C4;
    int i10 = i00 + WW * C4;
    int i11 = i10 + C4;
    int ip  = blk * C4 + cq;

    // Front-batched streaming loads: 10 independent reads (MLP_p1 = 10)
    float4 a0 = __ldcs(&x0[i00]);
    float4 a1 = __ldcs(&x0[i01]);
    float4 a2 = __ldcs(&x0[i10]);
    float4 a3 = __ldcs(&x0[i11]);
    float4 pv = __ldcs(&x1[ip]);
    float4 b0 = __ldcs(&x0[i00 + 8]);
    float4 b1 = __ldcs(&x0[i01 + 8]);
    float4 b2 = __ldcs(&x0[i10 + 8]);
    float4 b3 = __ldcs(&x0[i11 + 8]);
    float4 qv = __ldcs(&x1[ip + 8]);

    float4 fra, frb;
    unsigned maskA = 0, maskB = 0;

    SOLVE(a0, a1, a2, a3, pv, fra, maskA, x, 0);
    SOLVE(a0, a1, a2, a3, pv, fra, maskA, y, 4);
    SOLVE(a0, a1, a2, a3, pv, fra, maskA, z, 8);
    SOLVE(a0, a1, a2, a3, pv, fra, maskA, w, 12);

    SOLVE(b0, b1, b2, b3, qv, frb, maskB, x, 0);
    SOLVE(b0, b1, b2, b3, qv, frb, maskB, y, 4);
    SOLVE(b0, b1, b2, b3, qv, frb, maskB, z, 8);
    SOLVE(b0, b1, b2, b3, qv, frb, maskB, w, 12);

    // out0 (replaced-value map) — inputs overwritten in place
    __stcs(&out0[i00], a0);
    __stcs(&out0[i00 + 8], b0);
    __stcs(&out0[i01], a1);
    __stcs(&out0[i01 + 8], b1);
    __stcs(&out0[i10], a2);
    __stcs(&out0[i10 + 8], b2);
    __stcs(&out0[i11], a3);
    __stcs(&out0[i11 + 8], b3);

    // repl
    __stcs(&out1[ip], pv);
    __stcs(&out1[ip + 8], qv);

    // out3 (fraction map)
    {
        float4 f;
        OUT3_VEC(f, maskA, fra, 0); __stcs(&out2[i00], f);
        OUT3_VEC(f, maskB, frb, 0); __stcs(&out2[i00 + 8], f);
        OUT3_VEC(f, maskA, fra, 1); __stcs(&out2[i01], f);
        OUT3_VEC(f, maskB, frb, 1); __stcs(&out2[i01 + 8], f);
        OUT3_VEC(f, maskA, fra, 2); __stcs(&out2[i10], f);
        OUT3_VEC(f, maskB, frb, 2); __stcs(&out2[i10 + 8], f);
        OUT3_VEC(f, maskA, fra, 3); __stcs(&out2[i11], f);
        OUT3_VEC(f, maskB, frb, 3); __stcs(&out2[i11 + 8], f);
    }
}

extern "C" void kernel_launch(void* const* d_in, const int* in_sizes, int n_in,
                              void* d_out, int out_size) {
    const float* x0 = (const float*)d_in[0];
    const float* x1 = (const float*)d_in[1];
    float* out = (float*)d_out;

    const size_t N0 = (size_t)BB * HH * WW * CC;     // 33554432
    const size_t N1 = (size_t)BB * hh2 * ww2 * CC;   // 8388608

    float* out0 = out;
    float* out1 = out + N0;
    float* out2 = out + N0 + N1;

    const int total_threads = (BB * hh2 * ww2) * 8;  // 1048576
    const int block = 256;
    const int grid = total_threads / block;          // 4096

    unpool_ls_kernel<<<grid, block>>>((const float4*)x0, (const float4*)x1,
                                      (float4*)out0, (float4*)out1, (float4*)out2);
}